// round 3
// baseline (speedup 1.0000x reference)
#include <cuda_runtime.h>
#include <math.h>

#define BB 32
#define NN 1024
#define FF 64
#define HH 24
#define L2E 1.4426950408889634f

// Scratch (allocation-free: __device__ globals)
__device__ float g_Z[BB * NN * HH];     // relu(linear) activations, 3 MB
__device__ float g_r[BB * NN];          // row norms ||Z_n||
__device__ float g_t[BB * NN];          // t_n = log2(s_n) + m_n*log2e
__device__ float g_dinv[BB * NN];       // degree^-1/2
__device__ int   g_M[BB];               // per-batch max row norm (as int bits)

static __device__ __forceinline__ float ex2f_(float x) {
    float r; asm("ex2.approx.ftz.f32 %0, %1;" : "=f"(r) : "f"(x)); return r;
}
static __device__ __forceinline__ float lg2f_(float x) {
    float r; asm("lg2.approx.f32 %0, %1;" : "=f"(r) : "f"(x)); return r;
}
static __device__ __forceinline__ float rsq_(float x) {
    float r; asm("rsqrt.approx.f32 %0, %1;" : "=f"(r) : "f"(x)); return r;
}

// ---------------------------------------------------------------------------
// K0: zero the per-batch max accumulators (graph replays re-run this)
// ---------------------------------------------------------------------------
__global__ void k0_init() {
    if (threadIdx.x < BB) g_M[threadIdx.x] = 0;
}

// ---------------------------------------------------------------------------
// K1: Z = relu(xt @ W + b), row norms r_n, batch max M_b.
// Block = 64 rows, 256 threads (4 threads/row x 6 h-outputs each).
// ---------------------------------------------------------------------------
__global__ void __launch_bounds__(256) k1_linrelu(
    const float* __restrict__ xt, const float* __restrict__ W,
    const float* __restrict__ bias)
{
    __shared__ float xs[64][65];   // padded: avoid 8-way bank conflicts
    __shared__ float Ws[FF][HH];
    __shared__ float bs[HH];
    const int tid = threadIdx.x;
    const int base = blockIdx.x * 64;   // global row offset (never straddles batch: 1024%64==0)

    const float4* xt4 = (const float4*)(xt + (size_t)base * FF);
    for (int i = tid; i < 1024; i += 256) {
        float4 v = xt4[i];
        int row = i >> 4, c = (i & 15) << 2;
        xs[row][c] = v.x; xs[row][c + 1] = v.y; xs[row][c + 2] = v.z; xs[row][c + 3] = v.w;
    }
    for (int i = tid; i < FF * HH; i += 256) Ws[i / HH][i % HH] = W[i];
    if (tid < HH) bs[tid] = bias[tid];
    __syncthreads();

    const int row = tid >> 2, hg = tid & 3, h0 = hg * 6;
    float acc[6];
    #pragma unroll
    for (int j = 0; j < 6; j++) acc[j] = bs[h0 + j];
    #pragma unroll 8
    for (int k = 0; k < FF; k++) {
        float xa = xs[row][k];
        #pragma unroll
        for (int j = 0; j < 6; j++) acc[j] = fmaf(xa, Ws[k][h0 + j], acc[j]);
    }
    const int g = base + row;
    float ss = 0.f;
    #pragma unroll
    for (int j = 0; j < 6; j++) {
        float z = fmaxf(acc[j], 0.f);
        g_Z[(size_t)g * HH + h0 + j] = z;
        ss = fmaf(z, z, ss);
    }
    // reduce sum-of-squares across the 4 lanes sharing this row
    ss += __shfl_xor_sync(0xffffffffu, ss, 1);
    ss += __shfl_xor_sync(0xffffffffu, ss, 2);
    if (hg == 0) {
        float rn = sqrtf(ss);
        g_r[g] = rn;
        atomicMax(&g_M[base >> 10], __float_as_int(rn));  // rn >= 0: int order == float order
    }
}

// ---------------------------------------------------------------------------
// Shared gram-sweep skeleton: each block owns 128 rows of one batch.
// 8 warps: rhalf = w/4 selects rows [0,64) or [64,128); wc = w%4 splits columns.
// Each thread: 2 rows resident in registers (2x24 floats), sweeps 4 columns/iter.
// ---------------------------------------------------------------------------
#define GRAM_SETUP() \
    const int tid = threadIdx.x, w = tid >> 5, lane = tid & 31;      \
    const int b = blockIdx.x >> 3, ib = blockIdx.x & 7;              \
    const int rhalf = w >> 2, wc = w & 3;                            \
    const int nloc = rhalf * 64 + lane * 2;                          \
    const int grow = b * NN + ib * 128 + nloc;                       \
    float zr[2][24];                                                 \
    {                                                                \
        const float4* zg = (const float4*)g_Z;                       \
        _Pragma("unroll")                                            \
        for (int r = 0; r < 2; r++) {                                \
            _Pragma("unroll")                                        \
            for (int kk = 0; kk < 6; kk++) {                         \
                float4 v = zg[(size_t)(grow + r) * 6 + kk];          \
                zr[r][kk * 4 + 0] = v.x; zr[r][kk * 4 + 1] = v.y;    \
                zr[r][kk * 4 + 2] = v.z; zr[r][kk * 4 + 3] = v.w;    \
            }                                                        \
        }                                                            \
    }

#define GRAM_DOT(cb)                                                 \
    float a[2][4] = {};                                              \
    {                                                                \
        _Pragma("unroll")                                            \
        for (int kk = 0; kk < 6; kk++) {                             \
            float4 bq[4];                                            \
            _Pragma("unroll")                                        \
            for (int q = 0; q < 4; q++) bq[q] = Zc4[((cb) + q) * 6 + kk]; \
            _Pragma("unroll")                                        \
            for (int r = 0; r < 2; r++) {                            \
                _Pragma("unroll")                                    \
                for (int q = 0; q < 4; q++) {                        \
                    a[r][q] = fmaf(zr[r][kk * 4 + 0], bq[q].x, a[r][q]); \
                    a[r][q] = fmaf(zr[r][kk * 4 + 1], bq[q].y, a[r][q]); \
                    a[r][q] = fmaf(zr[r][kk * 4 + 2], bq[q].z, a[r][q]); \
                    a[r][q] = fmaf(zr[r][kk * 4 + 3], bq[q].w, a[r][q]); \
                }                                                    \
            }                                                        \
        }                                                            \
    }

// ---------------------------------------------------------------------------
// K2: s_n = sum_m exp(A[n,m] - m_n), with m_n = r_n * M_b (Cauchy-Schwarz bound,
// so no max pass). Writes t_n = log2(s_n) + m_n*log2e.
// ---------------------------------------------------------------------------
__global__ void __launch_bounds__(256) k2_rowsum() {
    __shared__ float Zc[256 * 24];
    __shared__ float sred[4][128];
    GRAM_SETUP();
    const float M = __int_as_float(g_M[b]);
    const float sh0 = g_r[grow]     * M * L2E;
    const float sh1 = g_r[grow + 1] * M * L2E;
    float s0 = 0.f, s1 = 0.f;
    float4* Zc4 = (float4*)Zc;
    const float4* zchunk = (const float4*)(g_Z + (size_t)b * NN * HH);

    for (int cs = 0; cs < NN; cs += 256) {
        __syncthreads();
        const float4* src = zchunk + (size_t)cs * 6;
        for (int i = tid; i < 1536; i += 256) Zc4[i] = src[i];
        __syncthreads();
        for (int j = 0; j < 16; j++) {
            const int cb = wc * 4 + j * 16;
            GRAM_DOT(cb);
            s0 += ex2f_(fmaf(a[0][0], L2E, -sh0)) + ex2f_(fmaf(a[0][1], L2E, -sh0))
                + ex2f_(fmaf(a[0][2], L2E, -sh0)) + ex2f_(fmaf(a[0][3], L2E, -sh0));
            s1 += ex2f_(fmaf(a[1][0], L2E, -sh1)) + ex2f_(fmaf(a[1][1], L2E, -sh1))
                + ex2f_(fmaf(a[1][2], L2E, -sh1)) + ex2f_(fmaf(a[1][3], L2E, -sh1));
        }
    }
    sred[wc][nloc] = s0;
    sred[wc][nloc + 1] = s1;
    __syncthreads();
    if (tid < 128) {
        float s = sred[0][tid] + sred[1][tid] + sred[2][tid] + sred[3][tid];
        int g = b * NN + ib * 128 + tid;
        g_t[g] = lg2f_(s) + g_r[g] * M * L2E;
    }
}

// ---------------------------------------------------------------------------
// K3: c_m = sum_n P[n,m] = sum_n exp2(A[m,n]*log2e - t_n)  (A symmetric, so the
// block owns 128 "m" rows and sweeps n with t_n from smem).
// Tail fuses the old K4: dinv_m = (0.5*(1+c_m) + 1)^-1/2  (degree >= 1.5, clip dead).
// ---------------------------------------------------------------------------
__global__ void __launch_bounds__(256) k3_colsum() {
    __shared__ float Zc[256 * 24];
    __shared__ float tcs[256];
    __shared__ float cred[4][128];
    GRAM_SETUP();
    float c0 = 0.f, c1 = 0.f;
    float4* Zc4 = (float4*)Zc;
    const float4* zchunk = (const float4*)(g_Z + (size_t)b * NN * HH);

    for (int cs = 0; cs < NN; cs += 256) {
        __syncthreads();
        const float4* src = zchunk + (size_t)cs * 6;
        for (int i = tid; i < 1536; i += 256) Zc4[i] = src[i];
        tcs[tid] = g_t[b * NN + cs + tid];
        __syncthreads();
        for (int j = 0; j < 16; j++) {
            const int cb = wc * 4 + j * 16;
            GRAM_DOT(cb);
            #pragma unroll
            for (int q = 0; q < 4; q++) {
                float tn = tcs[cb + q];
                c0 += ex2f_(fmaf(a[0][q], L2E, -tn));
                c1 += ex2f_(fmaf(a[1][q], L2E, -tn));
            }
        }
    }
    cred[wc][nloc] = c0;
    cred[wc][nloc + 1] = c1;
    __syncthreads();
    if (tid < 128) {
        float c = cred[0][tid] + cred[1][tid] + cred[2][tid] + cred[3][tid];
        g_dinv[b * NN + ib * 128 + tid] = rsq_(fmaf(0.5f, c, 1.5f));
    }
}

// ---------------------------------------------------------------------------
// K5: out[b,n,m] = (0.5*(exp2(aL - t_n) + exp2(aL - t_m)) + [n==m]) * dinv_n * dinv_m
// One gram pass; writes float4 per row.
// ---------------------------------------------------------------------------
__global__ void __launch_bounds__(256) k5_out(float* __restrict__ out) {
    __shared__ float Zc[256 * 24];
    __shared__ float tcs[256];
    __shared__ float dcs[256];
    GRAM_SETUP();
    const float t0 = g_t[grow],    t1 = g_t[grow + 1];
    const float d0 = g_dinv[grow], d1 = g_dinv[grow + 1];
    const int n0 = ib * 128 + nloc;  // batch-local row index
    float* ob = out + ((size_t)b << 20);
    float4* Zc4 = (float4*)Zc;
    const float4* zchunk = (const float4*)(g_Z + (size_t)b * NN * HH);

    for (int cs = 0; cs < NN; cs += 256) {
        __syncthreads();
        const float4* src = zchunk + (size_t)cs * 6;
        for (int i = tid; i < 1536; i += 256) Zc4[i] = src[i];
        tcs[tid] = g_t[b * NN + cs + tid];
        dcs[tid] = g_dinv[b * NN + cs + tid];
        __syncthreads();
        for (int j = 0; j < 16; j++) {
            const int cb = wc * 4 + j * 16;
            GRAM_DOT(cb);
            #pragma unroll
            for (int r = 0; r < 2; r++) {
                const float tr = r ? t1 : t0;
                const float dr = r ? d1 : d0;
                const int ng = n0 + r;
                float v[4];
                #pragma unroll
                for (int q = 0; q < 4; q++) {
                    float al = a[r][q] * L2E;
                    float e = 0.5f * (ex2f_(al - tr) + ex2f_(al - tcs[cb + q]));
                    if (ng == cs + cb + q) e += 1.0f;
                    v[q] = e * dr * dcs[cb + q];
                }
                *(float4*)(ob + (size_t)ng * NN + cs + cb) = make_float4(v[0], v[1], v[2], v[3]);
            }
        }
    }
}

// ---------------------------------------------------------------------------
extern "C" void kernel_launch(void* const* d_in, const int* in_sizes, int n_in,
                              void* d_out, int out_size)
{
    const float* xt = (const float*)d_in[0];   // (32, 1024, 64)
    const float* W  = (const float*)d_in[1];   // (64, 24)
    const float* bv = (const float*)d_in[2];   // (24,)
    float* out = (float*)d_out;                // (32, 1024, 1024)

    k0_init<<<1, 32>>>();
    k1_linrelu<<<512, 256>>>(xt, W, bv);
    k2_rowsum<<<256, 256>>>();
    k3_colsum<<<256, 256>>>();
    k5_out<<<256, 256>>>(out);
}

// round 4
// speedup vs baseline: 1.1477x; 1.1477x over previous
#include <cuda_runtime.h>
#include <math.h>

#define BB 32
#define NN 1024
#define FF 64
#define HH 24
#define L2E 1.4426950408889634f

// Scratch (allocation-free: __device__ globals)
__device__ float g_Z[BB * NN * HH];     // relu(linear) activations, 3 MB
__device__ float g_r[BB * NN];          // row norms ||Z_n||
__device__ float g_s[BB * NN];          // softmax denominators (atomic accum)
__device__ float g_t[BB * NN];          // t_n = log2(s_n) + m_n*log2e
__device__ float g_c[BB * NN];          // column sums of P (atomic accum)
__device__ float g_dinv[BB * NN];       // degree^-1/2
__device__ int   g_M[BB];               // per-batch max row norm (as int bits)

static __device__ __forceinline__ float ex2f_(float x) {
    float r; asm("ex2.approx.ftz.f32 %0, %1;" : "=f"(r) : "f"(x)); return r;
}
static __device__ __forceinline__ float lg2f_(float x) {
    float r; asm("lg2.approx.f32 %0, %1;" : "=f"(r) : "f"(x)); return r;
}
static __device__ __forceinline__ float rsq_(float x) {
    float r; asm("rsqrt.approx.f32 %0, %1;" : "=f"(r) : "f"(x)); return r;
}
static __device__ __forceinline__ float wsum_(float v) {
    v += __shfl_xor_sync(0xffffffffu, v, 16);
    v += __shfl_xor_sync(0xffffffffu, v, 8);
    v += __shfl_xor_sync(0xffffffffu, v, 4);
    v += __shfl_xor_sync(0xffffffffu, v, 2);
    v += __shfl_xor_sync(0xffffffffu, v, 1);
    return v;
}

// ---------------------------------------------------------------------------
// K0: zero atomic accumulators (graph replays re-run this)
// ---------------------------------------------------------------------------
__global__ void k0_init() {
    int g = blockIdx.x * 256 + threadIdx.x;           // 128 blocks x 256 = 32768
    g_s[g] = 0.f;
    g_c[g] = 0.f;
    if (g < BB) g_M[g] = 0;
}

// ---------------------------------------------------------------------------
// K1: Z = relu(xt @ W + b), row norms r_n, batch max M_b.
// ---------------------------------------------------------------------------
__global__ void __launch_bounds__(256) k1_linrelu(
    const float* __restrict__ xt, const float* __restrict__ W,
    const float* __restrict__ bias)
{
    __shared__ float xs[64][65];
    __shared__ float Ws[FF][HH];
    __shared__ float bs[HH];
    const int tid = threadIdx.x;
    const int base = blockIdx.x * 64;

    const float4* xt4 = (const float4*)(xt + (size_t)base * FF);
    for (int i = tid; i < 1024; i += 256) {
        float4 v = xt4[i];
        int row = i >> 4, c = (i & 15) << 2;
        xs[row][c] = v.x; xs[row][c + 1] = v.y; xs[row][c + 2] = v.z; xs[row][c + 3] = v.w;
    }
    for (int i = tid; i < FF * HH; i += 256) Ws[i / HH][i % HH] = W[i];
    if (tid < HH) bs[tid] = bias[tid];
    __syncthreads();

    const int row = tid >> 2, hg = tid & 3, h0 = hg * 6;
    float acc[6];
    #pragma unroll
    for (int j = 0; j < 6; j++) acc[j] = bs[h0 + j];
    #pragma unroll 8
    for (int k = 0; k < FF; k++) {
        float xa = xs[row][k];
        #pragma unroll
        for (int j = 0; j < 6; j++) acc[j] = fmaf(xa, Ws[k][h0 + j], acc[j]);
    }
    const int g = base + row;
    float ss = 0.f;
    #pragma unroll
    for (int j = 0; j < 6; j++) {
        float z = fmaxf(acc[j], 0.f);
        g_Z[(size_t)g * HH + h0 + j] = z;
        ss = fmaf(z, z, ss);
    }
    ss += __shfl_xor_sync(0xffffffffu, ss, 1);
    ss += __shfl_xor_sync(0xffffffffu, ss, 2);
    if (hg == 0) {
        float rn = sqrtf(ss);
        g_r[g] = rn;
        atomicMax(&g_M[base >> 10], __float_as_int(rn));
    }
}

// ---------------------------------------------------------------------------
// Triangular tile skeleton. grid = BB*36; tile t -> (ti, tj), ti >= tj.
// Register side: 128 rows of tile ti (2/thread). Smem side: 128 rows of tile tj.
// 8 warps = (2 row-halves) x (4 col groups); j-loop covers 32 cols/warp-group.
// ---------------------------------------------------------------------------
#define TILE_SETUP() \
    const int tid = threadIdx.x, w = tid >> 5, lane = tid & 31;      \
    const int b = blockIdx.x / 36, t = blockIdx.x % 36;              \
    int ti = (int)((sqrtf(8.f * t + 1.f) - 1.f) * 0.5f);             \
    while ((ti + 1) * (ti + 2) / 2 <= t) ti++;                       \
    while (ti * (ti + 1) / 2 > t) ti--;                              \
    const int tj = t - ti * (ti + 1) / 2;                            \
    const int rhalf = w >> 2, wc = w & 3;                            \
    const int nloc = rhalf * 64 + lane * 2;                          \
    const int growR = b * NN + ti * 128 + nloc;                      \
    const int colbase = b * NN + tj * 128;                           \
    float zr[2][24];                                                 \
    {                                                                \
        const float4* zg = (const float4*)g_Z;                       \
        _Pragma("unroll")                                            \
        for (int r = 0; r < 2; r++) {                                \
            _Pragma("unroll")                                        \
            for (int kk = 0; kk < 6; kk++) {                         \
                float4 v = zg[(size_t)(growR + r) * 6 + kk];         \
                zr[r][kk * 4 + 0] = v.x; zr[r][kk * 4 + 1] = v.y;    \
                zr[r][kk * 4 + 2] = v.z; zr[r][kk * 4 + 3] = v.w;    \
            }                                                        \
        }                                                            \
    }

#define TILE_LOAD_ZC() \
    {                                                                \
        const float4* src = (const float4*)(g_Z + (size_t)colbase * HH); \
        for (int i = tid; i < 768; i += 256) Zc4[i] = src[i];        \
    }

#define GRAM_DOT(cb)                                                 \
    float a[2][4] = {};                                              \
    {                                                                \
        _Pragma("unroll")                                            \
        for (int kk = 0; kk < 6; kk++) {                             \
            float4 bq[4];                                            \
            _Pragma("unroll")                                        \
            for (int q = 0; q < 4; q++) bq[q] = Zc4[((cb) + q) * 6 + kk]; \
            _Pragma("unroll")                                        \
            for (int r = 0; r < 2; r++) {                            \
                _Pragma("unroll")                                    \
                for (int q = 0; q < 4; q++) {                        \
                    a[r][q] = fmaf(zr[r][kk * 4 + 0], bq[q].x, a[r][q]); \
                    a[r][q] = fmaf(zr[r][kk * 4 + 1], bq[q].y, a[r][q]); \
                    a[r][q] = fmaf(zr[r][kk * 4 + 2], bq[q].z, a[r][q]); \
                    a[r][q] = fmaf(zr[r][kk * 4 + 3], bq[q].w, a[r][q]); \
                }                                                    \
            }                                                        \
        }                                                            \
    }

// ---------------------------------------------------------------------------
// K2: softmax denominators with Cauchy-Schwarz shift sh_n = r_n*M_b*log2e.
// Off-diag tiles feed BOTH s_n (reg rows, shift sh_n) and s_m (smem cols,
// shift sh_m) from one dot product. Results atomically accumulated in g_s.
// ---------------------------------------------------------------------------
__global__ void __launch_bounds__(256) k2_rowsum() {
    __shared__ float Zc[128 * 24];
    __shared__ float rcs[128];        // col-side shifts sh_m
    __shared__ float scol[2][128];    // col partials per row-half
    __shared__ float sred[4][128];
    float4* Zc4 = (float4*)Zc;
    TILE_SETUP();
    const float M = __int_as_float(g_M[b]);
    TILE_LOAD_ZC();
    if (tid < 128) rcs[tid] = g_r[colbase + tid] * M * L2E;
    scol[tid >> 7][tid & 127] = 0.f;
    const float sh0 = g_r[growR]     * M * L2E;
    const float sh1 = g_r[growR + 1] * M * L2E;
    float s0 = 0.f, s1 = 0.f;
    const bool offd = (ti != tj);
    __syncthreads();

    for (int j = 0; j < 8; j++) {
        const int cb = wc * 4 + j * 16;
        GRAM_DOT(cb);
        #pragma unroll
        for (int q = 0; q < 4; q++) {
            float al0 = a[0][q] * L2E, al1 = a[1][q] * L2E;
            s0 += ex2f_(al0 - sh0);
            s1 += ex2f_(al1 - sh1);
            if (offd) {
                float shm = rcs[cb + q];
                float ec = wsum_(ex2f_(al0 - shm) + ex2f_(al1 - shm));
                if (lane == 0) scol[rhalf][cb + q] += ec;
            }
        }
    }
    sred[wc][nloc] = s0;
    sred[wc][nloc + 1] = s1;
    __syncthreads();
    if (tid < 128) {
        float s = sred[0][tid] + sred[1][tid] + sred[2][tid] + sred[3][tid];
        atomicAdd(&g_s[b * NN + ti * 128 + tid], s);
        if (offd) atomicAdd(&g_s[colbase + tid], scol[0][tid] + scol[1][tid]);
    }
}

// K2 finisher: t_n = log2(s_n) + sh_n
__global__ void k2_fin() {
    int g = blockIdx.x * 256 + threadIdx.x;
    float M = __int_as_float(g_M[g >> 10]);
    g_t[g] = lg2f_(g_s[g]) + g_r[g] * M * L2E;
}

// ---------------------------------------------------------------------------
// K3: column sums of P. Row-accum: c_n += sum_m ex2(aL - t_m) (t from smem);
// off-diag also col-accum: c_m += sum_n ex2(aL - t_n) (t from regs).
// ---------------------------------------------------------------------------
__global__ void __launch_bounds__(256) k3_colsum() {
    __shared__ float Zc[128 * 24];
    __shared__ float tcs[128];
    __shared__ float scol[2][128];
    __shared__ float cred[4][128];
    float4* Zc4 = (float4*)Zc;
    TILE_SETUP();
    TILE_LOAD_ZC();
    if (tid < 128) tcs[tid] = g_t[colbase + tid];
    scol[tid >> 7][tid & 127] = 0.f;
    const float t0 = g_t[growR], t1 = g_t[growR + 1];
    float c0 = 0.f, c1 = 0.f;
    const bool offd = (ti != tj);
    __syncthreads();

    for (int j = 0; j < 8; j++) {
        const int cb = wc * 4 + j * 16;
        GRAM_DOT(cb);
        #pragma unroll
        for (int q = 0; q < 4; q++) {
            float al0 = a[0][q] * L2E, al1 = a[1][q] * L2E;
            float tm = tcs[cb + q];
            c0 += ex2f_(al0 - tm);
            c1 += ex2f_(al1 - tm);
            if (offd) {
                float ec = wsum_(ex2f_(al0 - t0) + ex2f_(al1 - t1));
                if (lane == 0) scol[rhalf][cb + q] += ec;
            }
        }
    }
    cred[wc][nloc] = c0;
    cred[wc][nloc + 1] = c1;
    __syncthreads();
    if (tid < 128) {
        float c = cred[0][tid] + cred[1][tid] + cred[2][tid] + cred[3][tid];
        atomicAdd(&g_c[b * NN + ti * 128 + tid], c);
        if (offd) atomicAdd(&g_c[colbase + tid], scol[0][tid] + scol[1][tid]);
    }
}

// K3 finisher: dinv = (0.5*(1+c) + 1)^-1/2  (degree >= 1.5, clip dead)
__global__ void k3_fin() {
    int g = blockIdx.x * 256 + threadIdx.x;
    g_dinv[g] = rsq_(fmaf(0.5f, g_c[g], 1.5f));
}

// ---------------------------------------------------------------------------
// K5: out[n,m] = (0.5*(ex2(aL-t_n)+ex2(aL-t_m)) + [n==m]) * d_n * d_m.
// Symmetric in (n,m): triangular tiles, mirror-write the transpose (float2
// over the thread's row pair -> coalesced).
// ---------------------------------------------------------------------------
__global__ void __launch_bounds__(256) k5_out(float* __restrict__ out) {
    __shared__ float Zc[128 * 24];
    __shared__ float tcs[128];
    __shared__ float dcs[128];
    float4* Zc4 = (float4*)Zc;
    TILE_SETUP();
    TILE_LOAD_ZC();
    if (tid < 128) {
        tcs[tid] = g_t[colbase + tid];
        dcs[tid] = g_dinv[colbase + tid];
    }
    const float t0 = g_t[growR],    t1 = g_t[growR + 1];
    const float d0 = g_dinv[growR], d1 = g_dinv[growR + 1];
    const int n0 = ti * 128 + nloc;          // batch-local row index
    const int m0base = tj * 128;             // batch-local col base
    const bool offd = (ti != tj);
    float* ob = out + ((size_t)b << 20);
    __syncthreads();

    for (int j = 0; j < 8; j++) {
        const int cb = wc * 4 + j * 16;
        GRAM_DOT(cb);
        float v[2][4];
        #pragma unroll
        for (int r = 0; r < 2; r++) {
            const float tr = r ? t1 : t0;
            const float dr = r ? d1 : d0;
            const int ng = n0 + r;
            #pragma unroll
            for (int q = 0; q < 4; q++) {
                float al = a[r][q] * L2E;
                float e = 0.5f * (ex2f_(al - tr) + ex2f_(al - tcs[cb + q]));
                if (ng == m0base + cb + q) e += 1.0f;
                v[r][q] = e * dr * dcs[cb + q];
            }
        }
        *(float4*)(ob + (size_t)(n0)     * NN + m0base + cb) = make_float4(v[0][0], v[0][1], v[0][2], v[0][3]);
        *(float4*)(ob + (size_t)(n0 + 1) * NN + m0base + cb) = make_float4(v[1][0], v[1][1], v[1][2], v[1][3]);
        if (offd) {
            #pragma unroll
            for (int q = 0; q < 4; q++)
                *(float2*)(ob + (size_t)(m0base + cb + q) * NN + n0) = make_float2(v[0][q], v[1][q]);
        }
    }
}

// ---------------------------------------------------------------------------
extern "C" void kernel_launch(void* const* d_in, const int* in_sizes, int n_in,
                              void* d_out, int out_size)
{
    const float* xt = (const float*)d_in[0];   // (32, 1024, 64)
    const float* W  = (const float*)d_in[1];   // (64, 24)
    const float* bv = (const float*)d_in[2];   // (24,)
    float* out = (float*)d_out;                // (32, 1024, 1024)

    k0_init<<<128, 256>>>();
    k1_linrelu<<<512, 256>>>(xt, W, bv);
    k2_rowsum<<<BB * 36, 256>>>();
    k2_fin<<<128, 256>>>();
    k3_colsum<<<BB * 36, 256>>>();
    k3_fin<<<128, 256>>>();
    k5_out<<<BB * 36, 256>>>(out);
}

// round 5
// speedup vs baseline: 1.1744x; 1.0233x over previous
#include <cuda_runtime.h>
#include <math.h>

#define BB 32
#define NN 1024
#define FF 64
#define HH 24
#define L2E 1.4426950408889634f

// Scratch (allocation-free: __device__ globals)
__device__ float g_Z[BB * NN * HH];       // relu(linear) activations, 3 MB
__device__ float g_A[BB * 36 * 16384];    // lower-tri gram tiles, thread-order, 75.5 MB
__device__ float g_r[BB * NN];            // row norms ||Z_n||
__device__ float g_s[BB * NN];            // softmax denominators (atomic accum)
__device__ float g_t[BB * NN];            // t_n = log2(s_n) + m_n*log2e
__device__ float g_c[BB * NN];            // column sums of P (atomic accum)
__device__ float g_dinv[BB * NN];         // degree^-1/2
__device__ int   g_M[BB];                 // per-batch max row norm (as int bits)

static __device__ __forceinline__ float ex2f_(float x) {
    float r; asm("ex2.approx.ftz.f32 %0, %1;" : "=f"(r) : "f"(x)); return r;
}
static __device__ __forceinline__ float lg2f_(float x) {
    float r; asm("lg2.approx.f32 %0, %1;" : "=f"(r) : "f"(x)); return r;
}
static __device__ __forceinline__ float rsq_(float x) {
    float r; asm("rsqrt.approx.f32 %0, %1;" : "=f"(r) : "f"(x)); return r;
}
static __device__ __forceinline__ float wsum_(float v) {
    v += __shfl_xor_sync(0xffffffffu, v, 16);
    v += __shfl_xor_sync(0xffffffffu, v, 8);
    v += __shfl_xor_sync(0xffffffffu, v, 4);
    v += __shfl_xor_sync(0xffffffffu, v, 2);
    v += __shfl_xor_sync(0xffffffffu, v, 1);
    return v;
}

// ---------------------------------------------------------------------------
// K0: zero atomic accumulators (graph replays re-run this)
// ---------------------------------------------------------------------------
__global__ void k0_init() {
    int g = blockIdx.x * 256 + threadIdx.x;           // 128 x 256 = 32768
    g_s[g] = 0.f;
    g_c[g] = 0.f;
    if (g < BB) g_M[g] = 0;
}

// ---------------------------------------------------------------------------
// K1: Z = relu(xt @ W + b), row norms r_n, batch max M_b.
// ---------------------------------------------------------------------------
__global__ void __launch_bounds__(256) k1_linrelu(
    const float* __restrict__ xt, const float* __restrict__ W,
    const float* __restrict__ bias)
{
    __shared__ float xs[64][65];
    __shared__ float Ws[FF][HH];
    __shared__ float bs[HH];
    const int tid = threadIdx.x;
    const int base = blockIdx.x * 64;

    const float4* xt4 = (const float4*)(xt + (size_t)base * FF);
    for (int i = tid; i < 1024; i += 256) {
        float4 v = xt4[i];
        int row = i >> 4, c = (i & 15) << 2;
        xs[row][c] = v.x; xs[row][c + 1] = v.y; xs[row][c + 2] = v.z; xs[row][c + 3] = v.w;
    }
    for (int i = tid; i < FF * HH; i += 256) Ws[i / HH][i % HH] = W[i];
    if (tid < HH) bs[tid] = bias[tid];
    __syncthreads();

    const int row = tid >> 2, hg = tid & 3, h0 = hg * 6;
    float acc[6];
    #pragma unroll
    for (int j = 0; j < 6; j++) acc[j] = bs[h0 + j];
    #pragma unroll 8
    for (int k = 0; k < FF; k++) {
        float xa = xs[row][k];
        #pragma unroll
        for (int j = 0; j < 6; j++) acc[j] = fmaf(xa, Ws[k][h0 + j], acc[j]);
    }
    const int g = base + row;
    float ss = 0.f;
    #pragma unroll
    for (int j = 0; j < 6; j++) {
        float z = fmaxf(acc[j], 0.f);
        g_Z[(size_t)g * HH + h0 + j] = z;
        ss = fmaf(z, z, ss);
    }
    ss += __shfl_xor_sync(0xffffffffu, ss, 1);
    ss += __shfl_xor_sync(0xffffffffu, ss, 2);
    if (hg == 0) {
        float rn = sqrtf(ss);
        g_r[g] = rn;
        atomicMax(&g_M[base >> 10], __float_as_int(rn));
    }
}

// ---------------------------------------------------------------------------
// Triangular tile skeleton (indices only). grid = BB*36; t -> (ti, tj), ti>=tj.
// 8 warps = (2 row-halves) x (4 col groups); thread owns rows nloc, nloc+1.
// ---------------------------------------------------------------------------
#define TILE_IDX() \
    const int tid = threadIdx.x, w = tid >> 5, lane = tid & 31;      \
    const int b = blockIdx.x / 36, t = blockIdx.x % 36;              \
    int ti = (int)((sqrtf(8.f * t + 1.f) - 1.f) * 0.5f);             \
    while ((ti + 1) * (ti + 2) / 2 <= t) ti++;                       \
    while (ti * (ti + 1) / 2 > t) ti--;                              \
    const int tj = t - ti * (ti + 1) / 2;                            \
    const int rhalf = w >> 2, wc = w & 3;                            \
    const int nloc = rhalf * 64 + lane * 2;                          \
    const int growR = b * NN + ti * 128 + nloc;                      \
    const int colbase = b * NN + tj * 128;                           \
    float* atile = g_A + ((size_t)blockIdx.x << 14);

#define TILE_ZR() \
    float zr[2][24];                                                 \
    {                                                                \
        const float4* zg = (const float4*)g_Z;                       \
        _Pragma("unroll")                                            \
        for (int r = 0; r < 2; r++) {                                \
            _Pragma("unroll")                                        \
            for (int kk = 0; kk < 6; kk++) {                         \
                float4 v = zg[(size_t)(growR + r) * 6 + kk];         \
                zr[r][kk * 4 + 0] = v.x; zr[r][kk * 4 + 1] = v.y;    \
                zr[r][kk * 4 + 2] = v.z; zr[r][kk * 4 + 3] = v.w;    \
            }                                                        \
        }                                                            \
    }

#define GRAM_DOT(cb)                                                 \
    float a[2][4] = {};                                              \
    {                                                                \
        _Pragma("unroll")                                            \
        for (int kk = 0; kk < 6; kk++) {                             \
            float4 bq[4];                                            \
            _Pragma("unroll")                                        \
            for (int q = 0; q < 4; q++) bq[q] = Zc4[((cb) + q) * 6 + kk]; \
            _Pragma("unroll")                                        \
            for (int r = 0; r < 2; r++) {                            \
                _Pragma("unroll")                                    \
                for (int q = 0; q < 4; q++) {                        \
                    a[r][q] = fmaf(zr[r][kk * 4 + 0], bq[q].x, a[r][q]); \
                    a[r][q] = fmaf(zr[r][kk * 4 + 1], bq[q].y, a[r][q]); \
                    a[r][q] = fmaf(zr[r][kk * 4 + 2], bq[q].z, a[r][q]); \
                    a[r][q] = fmaf(zr[r][kk * 4 + 3], bq[q].w, a[r][q]); \
                }                                                    \
            }                                                        \
        }                                                            \
    }

// Load the 8 a-values this thread produced in K2 (thread-order layout, coalesced)
#define LOAD_A(j)                                                    \
    float a[2][4];                                                   \
    {                                                                \
        const float4* ap = (const float4*)(atile + (((j) * 256 + tid) << 3)); \
        float4 v0 = ap[0], v1 = ap[1];                               \
        a[0][0] = v0.x; a[0][1] = v0.y; a[0][2] = v0.z; a[0][3] = v0.w; \
        a[1][0] = v1.x; a[1][1] = v1.y; a[1][2] = v1.z; a[1][3] = v1.w; \
    }

// ---------------------------------------------------------------------------
// K2: the ONLY gram pass. Computes a = <Z_n,Z_m> per tile, stores it to g_A
// (thread-order), and accumulates softmax denominators with Cauchy-Schwarz
// shifts sh_n = r_n*M_b*log2e (row side from regs, col side via warp reduce).
// ---------------------------------------------------------------------------
__global__ void __launch_bounds__(256) k2_rowsum() {
    __shared__ float Zc[128 * 24];
    __shared__ float rcs[128];        // col-side shifts sh_m
    __shared__ float scol[2][128];    // col partials per row-half
    __shared__ float sred[4][128];
    float4* Zc4 = (float4*)Zc;
    TILE_IDX();
    TILE_ZR();
    const float M = __int_as_float(g_M[b]);
    {
        const float4* src = (const float4*)(g_Z + (size_t)colbase * HH);
        for (int i = tid; i < 768; i += 256) Zc4[i] = src[i];
    }
    if (tid < 128) rcs[tid] = g_r[colbase + tid] * M * L2E;
    scol[tid >> 7][tid & 127] = 0.f;
    const float sh0 = g_r[growR]     * M * L2E;
    const float sh1 = g_r[growR + 1] * M * L2E;
    float s0 = 0.f, s1 = 0.f;
    const bool offd = (ti != tj);
    __syncthreads();

    for (int j = 0; j < 8; j++) {
        const int cb = wc * 4 + j * 16;
        GRAM_DOT(cb);
        // store the tile in thread order for K3/K5 (coalesced 32B/thread)
        float4* ap = (float4*)(atile + ((j * 256 + tid) << 3));
        ap[0] = make_float4(a[0][0], a[0][1], a[0][2], a[0][3]);
        ap[1] = make_float4(a[1][0], a[1][1], a[1][2], a[1][3]);
        #pragma unroll
        for (int q = 0; q < 4; q++) {
            float al0 = a[0][q] * L2E, al1 = a[1][q] * L2E;
            s0 += ex2f_(al0 - sh0);
            s1 += ex2f_(al1 - sh1);
            if (offd) {
                float shm = rcs[cb + q];
                float ec = wsum_(ex2f_(al0 - shm) + ex2f_(al1 - shm));
                if (lane == 0) scol[rhalf][cb + q] += ec;
            }
        }
    }
    sred[wc][nloc] = s0;
    sred[wc][nloc + 1] = s1;
    __syncthreads();
    if (tid < 128) {
        float s = sred[0][tid] + sred[1][tid] + sred[2][tid] + sred[3][tid];
        atomicAdd(&g_s[b * NN + ti * 128 + tid], s);
        if (offd) atomicAdd(&g_s[colbase + tid], scol[0][tid] + scol[1][tid]);
    }
}

// K2 finisher: t_n = log2(s_n) + sh_n
__global__ void k2_fin() {
    int g = blockIdx.x * 256 + threadIdx.x;
    float M = __int_as_float(g_M[g >> 10]);
    g_t[g] = lg2f_(g_s[g]) + g_r[g] * M * L2E;
}

// ---------------------------------------------------------------------------
// K3: column sums of P from STORED a (no gram recompute; memory + MUFU bound).
// ---------------------------------------------------------------------------
__global__ void __launch_bounds__(256) k3_colsum() {
    __shared__ float tcs[128];
    __shared__ float scol[2][128];
    __shared__ float cred[4][128];
    TILE_IDX();
    if (tid < 128) tcs[tid] = g_t[colbase + tid];
    scol[tid >> 7][tid & 127] = 0.f;
    const float t0 = g_t[growR], t1 = g_t[growR + 1];
    float c0 = 0.f, c1 = 0.f;
    const bool offd = (ti != tj);
    __syncthreads();

    for (int j = 0; j < 8; j++) {
        const int cb = wc * 4 + j * 16;
        LOAD_A(j);
        #pragma unroll
        for (int q = 0; q < 4; q++) {
            float al0 = a[0][q] * L2E, al1 = a[1][q] * L2E;
            float tm = tcs[cb + q];
            c0 += ex2f_(al0 - tm);
            c1 += ex2f_(al1 - tm);
            if (offd) {
                float ec = wsum_(ex2f_(al0 - t0) + ex2f_(al1 - t1));
                if (lane == 0) scol[rhalf][cb + q] += ec;
            }
        }
    }
    cred[wc][nloc] = c0;
    cred[wc][nloc + 1] = c1;
    __syncthreads();
    if (tid < 128) {
        float c = cred[0][tid] + cred[1][tid] + cred[2][tid] + cred[3][tid];
        atomicAdd(&g_c[b * NN + ti * 128 + tid], c);
        if (offd) atomicAdd(&g_c[colbase + tid], scol[0][tid] + scol[1][tid]);
    }
}

// K3 finisher: dinv = (0.5*(1+c) + 1)^-1/2  (degree >= 1.5, clip dead)
__global__ void k3_fin() {
    int g = blockIdx.x * 256 + threadIdx.x;
    g_dinv[g] = rsq_(fmaf(0.5f, g_c[g], 1.5f));
}

// ---------------------------------------------------------------------------
// K5: out from STORED a. out[n,m] = (0.5*(ex2(aL-t_n)+ex2(aL-t_m)) + [n==m])
//     * d_n * d_m; mirror-write the transpose (float2 over row pair, 256B/warp).
// ---------------------------------------------------------------------------
__global__ void __launch_bounds__(256) k5_out(float* __restrict__ out) {
    __shared__ float tcs[128];
    __shared__ float dcs[128];
    TILE_IDX();
    if (tid < 128) {
        tcs[tid] = g_t[colbase + tid];
        dcs[tid] = g_dinv[colbase + tid];
    }
    const float t0 = g_t[growR],    t1 = g_t[growR + 1];
    const float d0 = g_dinv[growR], d1 = g_dinv[growR + 1];
    const int n0 = ti * 128 + nloc;          // batch-local row index
    const int m0base = tj * 128;             // batch-local col base
    const bool offd = (ti != tj);
    float* ob = out + ((size_t)b << 20);
    __syncthreads();

    for (int j = 0; j < 8; j++) {
        const int cb = wc * 4 + j * 16;
        LOAD_A(j);
        float v[2][4];
        #pragma unroll
        for (int r = 0; r < 2; r++) {
            const float tr = r ? t1 : t0;
            const float dr = r ? d1 : d0;
            const int ng = n0 + r;
            #pragma unroll
            for (int q = 0; q < 4; q++) {
                float al = a[r][q] * L2E;
                float e = 0.5f * (ex2f_(al - tr) + ex2f_(al - tcs[cb + q]));
                if (ng == m0base + cb + q) e += 1.0f;
                v[r][q] = e * dr * dcs[cb + q];
            }
        }
        *(float4*)(ob + (size_t)(n0)     * NN + m0base + cb) = make_float4(v[0][0], v[0][1], v[0][2], v[0][3]);
        *(float4*)(ob + (size_t)(n0 + 1) * NN + m0base + cb) = make_float4(v[1][0], v[1][1], v[1][2], v[1][3]);
        if (offd) {
            #pragma unroll
            for (int q = 0; q < 4; q++)
                *(float2*)(ob + (size_t)(m0base + cb + q) * NN + n0) = make_float2(v[0][q], v[1][q]);
        }
    }
}

// ---------------------------------------------------------------------------
extern "C" void kernel_launch(void* const* d_in, const int* in_sizes, int n_in,
                              void* d_out, int out_size)
{
    const float* xt = (const float*)d_in[0];   // (32, 1024, 64)
    const float* W  = (const float*)d_in[1];   // (64, 24)
    const float* bv = (const float*)d_in[2];   // (24,)
    float* out = (float*)d_out;                // (32, 1024, 1024)

    k0_init<<<128, 256>>>();
    k1_linrelu<<<512, 256>>>(xt, W, bv);
    k2_rowsum<<<BB * 36, 256>>>();
    k2_fin<<<128, 256>>>();
    k3_colsum<<<BB * 36, 256>>>();
    k3_fin<<<128, 256>>>();
    k5_out<<<BB * 36, 256>>>(out);
}

// round 6
// speedup vs baseline: 1.2064x; 1.0272x over previous
#include <cuda_runtime.h>
#include <math.h>

#define BB 32
#define NN 1024
#define FF 64
#define HH 24
#define L2E 1.4426950408889634f

// Scratch (allocation-free: __device__ globals)
__device__ float g_Z[BB * NN * HH];       // relu(linear) activations, 3 MB
__device__ float g_G[BB * 36 * 16384];    // lower-tri tiles of g=exp2(aL-C), thread-order, 75.5 MB
__device__ float g_s[BB * NN];            // S_n = sum_m g (atomic accum)
__device__ float g_c[BB * NN];            // c_n = sum_m P_mn (atomic accum)
__device__ int   g_M[BB];                 // per-batch max row norm (bits; atomicMax is replay-idempotent)

static __device__ __forceinline__ float ex2f_(float x) {
    float r; asm("ex2.approx.ftz.f32 %0, %1;" : "=f"(r) : "f"(x)); return r;
}
static __device__ __forceinline__ float rsq_(float x) {
    float r; asm("rsqrt.approx.f32 %0, %1;" : "=f"(r) : "f"(x)); return r;
}

// Butterfly transpose-reduce: 32 per-thread col partials -> lane l holds the
// 32-lane sum for slot l. 31 shuffles total.
static __device__ __forceinline__ float butterfly32_(float* c, int lane) {
    #pragma unroll
    for (int m = 16; m >= 1; m >>= 1) {
        const bool hi = (lane & m) != 0;
        #pragma unroll
        for (int i = 0; i < m; i++) {
            float sent = hi ? c[i] : c[i + m];
            float recv = __shfl_xor_sync(0xffffffffu, sent, m);
            c[i] = (hi ? c[i + m] : c[i]) + recv;
        }
    }
    return c[0];
}

// ---------------------------------------------------------------------------
// K1: Z = relu(xt @ W + b), batch max norm M_b; also zeroes g_s/g_c.
// ---------------------------------------------------------------------------
__global__ void __launch_bounds__(256) k1_linrelu(
    const float* __restrict__ xt, const float* __restrict__ W,
    const float* __restrict__ bias)
{
    __shared__ float xs[64][65];
    __shared__ float Ws[FF][HH];
    __shared__ float bs[HH];
    const int tid = threadIdx.x;
    const int base = blockIdx.x * 64;

    if (tid < 64) {                       // 512 blocks x 64 = 32768: zero accumulators
        g_s[base + tid] = 0.f;
        g_c[base + tid] = 0.f;
    }

    const float4* xt4 = (const float4*)(xt + (size_t)base * FF);
    for (int i = tid; i < 1024; i += 256) {
        float4 v = xt4[i];
        int row = i >> 4, c = (i & 15) << 2;
        xs[row][c] = v.x; xs[row][c + 1] = v.y; xs[row][c + 2] = v.z; xs[row][c + 3] = v.w;
    }
    for (int i = tid; i < FF * HH; i += 256) Ws[i / HH][i % HH] = W[i];
    if (tid < HH) bs[tid] = bias[tid];
    __syncthreads();

    const int row = tid >> 2, hg = tid & 3, h0 = hg * 6;
    float acc[6];
    #pragma unroll
    for (int j = 0; j < 6; j++) acc[j] = bs[h0 + j];
    #pragma unroll 8
    for (int k = 0; k < FF; k++) {
        float xa = xs[row][k];
        #pragma unroll
        for (int j = 0; j < 6; j++) acc[j] = fmaf(xa, Ws[k][h0 + j], acc[j]);
    }
    const int g = base + row;
    float ss = 0.f;
    #pragma unroll
    for (int j = 0; j < 6; j++) {
        float z = fmaxf(acc[j], 0.f);
        g_Z[(size_t)g * HH + h0 + j] = z;
        ss = fmaf(z, z, ss);
    }
    ss += __shfl_xor_sync(0xffffffffu, ss, 1);
    ss += __shfl_xor_sync(0xffffffffu, ss, 2);
    if (hg == 0) {
        float rn = sqrtf(ss);
        atomicMax(&g_M[base >> 10], __float_as_int(rn));  // rn>=0: int order == float order
    }
}

// ---------------------------------------------------------------------------
// Triangular tile indices. grid = BB*36; t -> (ti, tj), ti >= tj.
// 8 warps = (2 row-halves) x (4 col groups); thread owns rows nloc, nloc+1.
// ---------------------------------------------------------------------------
#define TILE_IDX() \
    const int tid = threadIdx.x, w = tid >> 5, lane = tid & 31;      \
    const int b = blockIdx.x / 36, t = blockIdx.x % 36;              \
    int ti = (int)((sqrtf(8.f * t + 1.f) - 1.f) * 0.5f);             \
    while ((ti + 1) * (ti + 2) / 2 <= t) ti++;                       \
    while (ti * (ti + 1) / 2 > t) ti--;                              \
    const int tj = t - ti * (ti + 1) / 2;                            \
    const int rhalf = w >> 2, wc = w & 3;                            \
    const int nloc = rhalf * 64 + lane * 2;                          \
    const int growR = b * NN + ti * 128 + nloc;                      \
    const int colbase = b * NN + tj * 128;                           \
    float* gtile = g_G + ((size_t)blockIdx.x << 14);                 \
    const bool offd = (ti != tj);

#define TILE_ZR() \
    float zr[2][24];                                                 \
    {                                                                \
        const float4* zg = (const float4*)g_Z;                       \
        _Pragma("unroll")                                            \
        for (int r = 0; r < 2; r++) {                                \
            _Pragma("unroll")                                        \
            for (int kk = 0; kk < 6; kk++) {                         \
                float4 v = zg[(size_t)(growR + r) * 6 + kk];         \
                zr[r][kk * 4 + 0] = v.x; zr[r][kk * 4 + 1] = v.y;    \
                zr[r][kk * 4 + 2] = v.z; zr[r][kk * 4 + 3] = v.w;    \
            }                                                        \
        }                                                            \
    }

#define GRAM_DOT(cb)                                                 \
    float a[2][4] = {};                                              \
    {                                                                \
        _Pragma("unroll")                                            \
        for (int kk = 0; kk < 6; kk++) {                             \
            float4 bq[4];                                            \
            _Pragma("unroll")                                        \
            for (int q = 0; q < 4; q++) bq[q] = Zc4[((cb) + q) * 6 + kk]; \
            _Pragma("unroll")                                        \
            for (int r = 0; r < 2; r++) {                            \
                _Pragma("unroll")                                    \
                for (int q = 0; q < 4; q++) {                        \
                    a[r][q] = fmaf(zr[r][kk * 4 + 0], bq[q].x, a[r][q]); \
                    a[r][q] = fmaf(zr[r][kk * 4 + 1], bq[q].y, a[r][q]); \
                    a[r][q] = fmaf(zr[r][kk * 4 + 2], bq[q].z, a[r][q]); \
                    a[r][q] = fmaf(zr[r][kk * 4 + 3], bq[q].w, a[r][q]); \
                }                                                    \
            }                                                        \
        }                                                            \
    }

// Load the 8 g-values this thread produced in K2 (thread-order, coalesced)
#define LOAD_G(j)                                                    \
    float gv[2][4];                                                  \
    {                                                                \
        const float4* gp = (const float4*)(gtile + (((j) * 256 + tid) << 3)); \
        float4 v0 = gp[0], v1 = gp[1];                               \
        gv[0][0] = v0.x; gv[0][1] = v0.y; gv[0][2] = v0.z; gv[0][3] = v0.w; \
        gv[1][0] = v1.x; gv[1][1] = v1.y; gv[1][2] = v1.z; gv[1][3] = v1.w; \
    }

// ---------------------------------------------------------------------------
// K2: the only gram pass. a = <Z_n,Z_m>; g = exp2(a*L2E - C), C = M_b^2*L2E
// (g <= 1, S <= 1024: overflow-free). Stores g; accumulates S_n = sum g for
// rows (reg side) and, off-diag, for cols via register partials + butterfly.
// ---------------------------------------------------------------------------
__global__ void __launch_bounds__(256) k2_gram() {
    __shared__ float Zc[128 * 24];
    __shared__ float sred[4][128];
    __shared__ float scol[2][128];
    float4* Zc4 = (float4*)Zc;
    TILE_IDX();
    TILE_ZR();
    const float M = __int_as_float(g_M[b]);
    const float C = M * M * L2E;
    {
        const float4* src = (const float4*)(g_Z + (size_t)colbase * HH);
        for (int i = tid; i < 768; i += 256) Zc4[i] = src[i];
    }
    float s0 = 0.f, s1 = 0.f;
    float ccol[32];
    #pragma unroll
    for (int i = 0; i < 32; i++) ccol[i] = 0.f;
    __syncthreads();

    #pragma unroll 2
    for (int j = 0; j < 8; j++) {
        const int cb = wc * 4 + j * 16;
        GRAM_DOT(cb);
        float g0[4], g1[4];
        #pragma unroll
        for (int q = 0; q < 4; q++) {
            g0[q] = ex2f_(fmaf(a[0][q], L2E, -C));
            g1[q] = ex2f_(fmaf(a[1][q], L2E, -C));
        }
        float4* gp = (float4*)(gtile + ((j * 256 + tid) << 3));
        gp[0] = make_float4(g0[0], g0[1], g0[2], g0[3]);
        gp[1] = make_float4(g1[0], g1[1], g1[2], g1[3]);
        #pragma unroll
        for (int q = 0; q < 4; q++) {
            s0 += g0[q];
            s1 += g1[q];
            ccol[j * 4 + q] += g0[q] + g1[q];
        }
    }
    sred[wc][nloc] = s0;
    sred[wc][nloc + 1] = s1;
    if (offd) {
        float cs = butterfly32_(ccol, lane);
        scol[rhalf][wc * 4 + (lane & 3) + 16 * (lane >> 2)] = cs;
    }
    __syncthreads();
    if (tid < 128) {
        float s = sred[0][tid] + sred[1][tid] + sred[2][tid] + sred[3][tid];
        atomicAdd(&g_s[b * NN + ti * 128 + tid], s);
        if (offd) atomicAdd(&g_s[colbase + tid], scol[0][tid] + scol[1][tid]);
    }
}

// ---------------------------------------------------------------------------
// K3: column sums of P from stored g. P_nm = g*w_n, w = 1/S.
// Row side: c_n += sum_m g*w_m (w from smem). Off-diag col side: c_m += g*w_n.
// ---------------------------------------------------------------------------
__global__ void __launch_bounds__(256) k3_colsum() {
    __shared__ float wv[128];
    __shared__ float cred[4][128];
    __shared__ float scol[2][128];
    TILE_IDX();
    if (tid < 128) wv[tid] = 1.0f / g_s[colbase + tid];
    const float w0 = 1.0f / g_s[growR];
    const float w1 = 1.0f / g_s[growR + 1];
    float c0 = 0.f, c1 = 0.f;
    float ccol[32];
    #pragma unroll
    for (int i = 0; i < 32; i++) ccol[i] = 0.f;
    __syncthreads();

    #pragma unroll 2
    for (int j = 0; j < 8; j++) {
        const int cb = wc * 4 + j * 16;
        LOAD_G(j);
        #pragma unroll
        for (int q = 0; q < 4; q++) {
            float wm = wv[cb + q];
            c0 = fmaf(gv[0][q], wm, c0);
            c1 = fmaf(gv[1][q], wm, c1);
            ccol[j * 4 + q] += fmaf(gv[0][q], w0, gv[1][q] * w1);
        }
    }
    cred[wc][nloc] = c0;
    cred[wc][nloc + 1] = c1;
    if (offd) {
        float cs = butterfly32_(ccol, lane);
        scol[rhalf][wc * 4 + (lane & 3) + 16 * (lane >> 2)] = cs;
    }
    __syncthreads();
    if (tid < 128) {
        float c = cred[0][tid] + cred[1][tid] + cred[2][tid] + cred[3][tid];
        atomicAdd(&g_c[b * NN + ti * 128 + tid], c);
        if (offd) atomicAdd(&g_c[colbase + tid], scol[0][tid] + scol[1][tid]);
    }
}

// ---------------------------------------------------------------------------
// K5: out[n,m] = g*(p_n*d_m + p_m*d_n) + [n==m]*d_n*d_m,
//     p = 0.5*w*d, d = rsqrt(0.5*c + 1.5). Mirror-writes the transpose.
// ---------------------------------------------------------------------------
__global__ void __launch_bounds__(256) k5_out(float* __restrict__ out) {
    __shared__ float dcs[128];
    __shared__ float pcs[128];
    TILE_IDX();
    if (tid < 128) {
        float wm = 1.0f / g_s[colbase + tid];
        float dm = rsq_(fmaf(0.5f, g_c[colbase + tid], 1.5f));
        dcs[tid] = dm;
        pcs[tid] = 0.5f * wm * dm;
    }
    const float d0 = rsq_(fmaf(0.5f, g_c[growR], 1.5f));
    const float d1 = rsq_(fmaf(0.5f, g_c[growR + 1], 1.5f));
    const float p0 = 0.5f * d0 / g_s[growR];
    const float p1 = 0.5f * d1 / g_s[growR + 1];
    const int n0 = ti * 128 + nloc;
    const int m0base = tj * 128;
    float* ob = out + ((size_t)b << 20);
    __syncthreads();

    #pragma unroll 2
    for (int j = 0; j < 8; j++) {
        const int cb = wc * 4 + j * 16;
        LOAD_G(j);
        float v[2][4];
        #pragma unroll
        for (int q = 0; q < 4; q++) {
            const float dm = dcs[cb + q], pm = pcs[cb + q];
            v[0][q] = gv[0][q] * fmaf(p0, dm, pm * d0);
            v[1][q] = gv[1][q] * fmaf(p1, dm, pm * d1);
            if (!offd) {   // diagonal tile: self-loop term
                if (n0 == m0base + cb + q)     v[0][q] = fmaf(d0, dm, v[0][q]);
                if (n0 + 1 == m0base + cb + q) v[1][q] = fmaf(d1, dm, v[1][q]);
            }
        }
        *(float4*)(ob + (size_t)(n0)     * NN + m0base + cb) = make_float4(v[0][0], v[0][1], v[0][2], v[0][3]);
        *(float4*)(ob + (size_t)(n0 + 1) * NN + m0base + cb) = make_float4(v[1][0], v[1][1], v[1][2], v[1][3]);
        if (offd) {
            #pragma unroll
            for (int q = 0; q < 4; q++)
                *(float2*)(ob + (size_t)(m0base + cb + q) * NN + n0) = make_float2(v[0][q], v[1][q]);
        }
    }
}

// ---------------------------------------------------------------------------
extern "C" void kernel_launch(void* const* d_in, const int* in_sizes, int n_in,
                              void* d_out, int out_size)
{
    const float* xt = (const float*)d_in[0];   // (32, 1024, 64)
    const float* W  = (const float*)d_in[1];   // (64, 24)
    const float* bv = (const float*)d_in[2];   // (24,)
    float* out = (float*)d_out;                // (32, 1024, 1024)

    k1_linrelu<<<512, 256>>>(xt, W, bv);
    k2_gram<<<BB * 36, 256>>>();
    k3_colsum<<<BB * 36, 256>>>();
    k5_out<<<BB * 36, 256>>>(out);
}

// round 7
// speedup vs baseline: 1.7676x; 1.4651x over previous
#include <cuda_runtime.h>
#include <math.h>

#define BB 32
#define NN 1024
#define FF 64
#define HH 24
#define L2E 1.4426950408889634f

// Scratch (allocation-free: __device__ globals)
__device__ float g_Z[BB * NN * HH];       // relu(linear) activations, 3 MB
__device__ float g_G[BB * 36 * 16384];    // lower-tri tiles of g=exp2(aL-C), K2-thread-order, 75.5 MB
__device__ float g_s[BB * NN];            // S_n = sum_m g (atomic accum)
__device__ float g_c[BB * NN];            // c_n = sum_m P_mn (atomic accum)
__device__ int   g_M[BB];                 // per-batch max row norm (bits; atomicMax replay-idempotent)

static __device__ __forceinline__ float ex2f_(float x) {
    float r; asm("ex2.approx.ftz.f32 %0, %1;" : "=f"(r) : "f"(x)); return r;
}
static __device__ __forceinline__ float rsq_(float x) {
    float r; asm("rsqrt.approx.f32 %0, %1;" : "=f"(r) : "f"(x)); return r;
}

// Butterfly transpose-reduce: 32 per-thread slot partials -> lane l holds the
// 32-lane sum of slot l (identity slot mapping; verified rounds 5-6).
static __device__ __forceinline__ float butterfly32_(float* c, int lane) {
    #pragma unroll
    for (int m = 16; m >= 1; m >>= 1) {
        const bool hi = (lane & m) != 0;
        #pragma unroll
        for (int i = 0; i < m; i++) {
            float sent = hi ? c[i] : c[i + m];
            float recv = __shfl_xor_sync(0xffffffffu, sent, m);
            c[i] = (hi ? c[i + m] : c[i]) + recv;
        }
    }
    return c[0];
}

// ---------------------------------------------------------------------------
// K1: Z = relu(xt @ W + b), batch max norm M_b; also zeroes g_s/g_c.
// ---------------------------------------------------------------------------
__global__ void __launch_bounds__(256) k1_linrelu(
    const float* __restrict__ xt, const float* __restrict__ W,
    const float* __restrict__ bias)
{
    __shared__ float xs[64][65];
    __shared__ float Ws[FF][HH];
    __shared__ float bs[HH];
    const int tid = threadIdx.x;
    const int base = blockIdx.x * 64;

    if (tid < 64) {                       // 512 blocks x 64 = 32768: zero accumulators
        g_s[base + tid] = 0.f;
        g_c[base + tid] = 0.f;
    }

    const float4* xt4 = (const float4*)(xt + (size_t)base * FF);
    for (int i = tid; i < 1024; i += 256) {
        float4 v = xt4[i];
        int row = i >> 4, c = (i & 15) << 2;
        xs[row][c] = v.x; xs[row][c + 1] = v.y; xs[row][c + 2] = v.z; xs[row][c + 3] = v.w;
    }
    for (int i = tid; i < FF * HH; i += 256) Ws[i / HH][i % HH] = W[i];
    if (tid < HH) bs[tid] = bias[tid];
    __syncthreads();

    const int row = tid >> 2, hg = tid & 3, h0 = hg * 6;
    float acc[6];
    #pragma unroll
    for (int j = 0; j < 6; j++) acc[j] = bs[h0 + j];
    #pragma unroll 8
    for (int k = 0; k < FF; k++) {
        float xa = xs[row][k];
        #pragma unroll
        for (int j = 0; j < 6; j++) acc[j] = fmaf(xa, Ws[k][h0 + j], acc[j]);
    }
    const int g = base + row;
    float ss = 0.f;
    #pragma unroll
    for (int j = 0; j < 6; j++) {
        float z = fmaxf(acc[j], 0.f);
        g_Z[(size_t)g * HH + h0 + j] = z;
        ss = fmaf(z, z, ss);
    }
    ss += __shfl_xor_sync(0xffffffffu, ss, 1);
    ss += __shfl_xor_sync(0xffffffffu, ss, 2);
    if (hg == 0) {
        float rn = sqrtf(ss);
        atomicMax(&g_M[base >> 10], __float_as_int(rn));  // rn>=0: int order == float order
    }
}

// ---------------------------------------------------------------------------
// Common triangular tile indices. grid = BB*36; t -> (ti, tj), ti >= tj.
// ---------------------------------------------------------------------------
#define TILE_COMMON() \
    const int tid = threadIdx.x, w = tid >> 5, lane = tid & 31;      \
    const int b = blockIdx.x / 36, t = blockIdx.x % 36;              \
    int ti = (int)((sqrtf(8.f * t + 1.f) - 1.f) * 0.5f);             \
    while ((ti + 1) * (ti + 2) / 2 <= t) ti++;                       \
    while (ti * (ti + 1) / 2 > t) ti--;                              \
    const int tj = t - ti * (ti + 1) / 2;                            \
    const int colbase = b * NN + tj * 128;                           \
    float* gtile = g_G + ((size_t)blockIdx.x << 14);                 \
    const bool offd = (ti != tj);

// K2 (producer) warp decomposition: 8 warps = rhalf(2) x wc(4)
#define TILE_IDX() \
    TILE_COMMON();                                                   \
    const int rhalf = w >> 2, wc = w & 3;                            \
    const int nloc = rhalf * 64 + lane * 2;                          \
    const int growR = b * NN + ti * 128 + nloc;

// Consumer (K3/K5) warp decomposition: 8 warps = rhalf(2) x wc2(2) x jw(2).
// Thread owns rows nloc,nloc+1 and, per jj, 8 consecutive cols
// cb = (jw*4+jj)*16 + wc2*8 -- two adjacent K2 chunks.
#define TILE_IDX2() \
    TILE_COMMON();                                                   \
    const int rhalf = w >> 2, wc2 = w & 1, jw = (w >> 1) & 1;        \
    const int nloc = rhalf * 64 + lane * 2;                          \
    const int growR = b * NN + ti * 128 + nloc;

#define TILE_ZR() \
    float zr[2][24];                                                 \
    {                                                                \
        const float4* zg = (const float4*)g_Z;                       \
        _Pragma("unroll")                                            \
        for (int r = 0; r < 2; r++) {                                \
            _Pragma("unroll")                                        \
            for (int kk = 0; kk < 6; kk++) {                         \
                float4 v = zg[(size_t)(growR + r) * 6 + kk];         \
                zr[r][kk * 4 + 0] = v.x; zr[r][kk * 4 + 1] = v.y;    \
                zr[r][kk * 4 + 2] = v.z; zr[r][kk * 4 + 3] = v.w;    \
            }                                                        \
        }                                                            \
    }

#define GRAM_DOT(cb)                                                 \
    float a[2][4] = {};                                              \
    {                                                                \
        _Pragma("unroll")                                            \
        for (int kk = 0; kk < 6; kk++) {                             \
            float4 bq[4];                                            \
            _Pragma("unroll")                                        \
            for (int q = 0; q < 4; q++) bq[q] = Zc4[((cb) + q) * 6 + kk]; \
            _Pragma("unroll")                                        \
            for (int r = 0; r < 2; r++) {                            \
                _Pragma("unroll")                                    \
                for (int q = 0; q < 4; q++) {                        \
                    a[r][q] = fmaf(zr[r][kk * 4 + 0], bq[q].x, a[r][q]); \
                    a[r][q] = fmaf(zr[r][kk * 4 + 1], bq[q].y, a[r][q]); \
                    a[r][q] = fmaf(zr[r][kk * 4 + 2], bq[q].z, a[r][q]); \
                    a[r][q] = fmaf(zr[r][kk * 4 + 3], bq[q].w, a[r][q]); \
                }                                                    \
            }                                                        \
        }                                                            \
    }

// Consumer: hoisted loads of all 16 g-float4s (rows n0,n0+1; 8 cols per jj).
// Chunk math: K2 thread (w2 = rhalf*4+wc, lane) stored float4 pair at index
// (j*256 + w2*32 + lane)*2; cols cb..cb+3 come from wc=2*wc2 (s=0), cb+4..7
// from wc=2*wc2+1 (s=1, +64 float4s).
#define LOAD_G_ALL()                                                 \
    float4 G[4][4];                                                  \
    {                                                                \
        const float4* gp = (const float4*)gtile;                     \
        _Pragma("unroll")                                            \
        for (int jj = 0; jj < 4; jj++) {                             \
            const int j = jw * 4 + jj;                               \
            const int b4 = (j * 256 + (rhalf * 4 + wc2 * 2) * 32 + lane) * 2; \
            G[jj][0] = gp[b4];      G[jj][1] = gp[b4 + 1];           \
            G[jj][2] = gp[b4 + 64]; G[jj][3] = gp[b4 + 65];          \
        }                                                            \
    }

#define UNPACK_G(jj)                                                 \
    float a0[8], a1[8];                                              \
    a0[0] = G[jj][0].x; a0[1] = G[jj][0].y; a0[2] = G[jj][0].z; a0[3] = G[jj][0].w; \
    a0[4] = G[jj][2].x; a0[5] = G[jj][2].y; a0[6] = G[jj][2].z; a0[7] = G[jj][2].w; \
    a1[0] = G[jj][1].x; a1[1] = G[jj][1].y; a1[2] = G[jj][1].z; a1[3] = G[jj][1].w; \
    a1[4] = G[jj][3].x; a1[5] = G[jj][3].y; a1[6] = G[jj][3].z; a1[7] = G[jj][3].w;

// ---------------------------------------------------------------------------
// K2: the only gram pass. a = <Z_n,Z_m>; g = exp2(a*L2E - C), C = M_b^2*L2E
// (g <= 1, S <= 1024: overflow-free). Stores g; accumulates S_n row-side
// (regs) and, off-diag, col-side via register partials + butterfly.
// ---------------------------------------------------------------------------
__global__ void __launch_bounds__(256) k2_gram() {
    __shared__ float Zc[128 * 24];
    __shared__ float sred[4][128];
    __shared__ float scol[2][128];
    float4* Zc4 = (float4*)Zc;
    TILE_IDX();
    TILE_ZR();
    const float M = __int_as_float(g_M[b]);
    const float C = M * M * L2E;
    {
        const float4* src = (const float4*)(g_Z + (size_t)colbase * HH);
        for (int i = tid; i < 768; i += 256) Zc4[i] = src[i];
    }
    float s0 = 0.f, s1 = 0.f;
    float ccol[32];
    #pragma unroll
    for (int i = 0; i < 32; i++) ccol[i] = 0.f;
    __syncthreads();

    #pragma unroll 2
    for (int j = 0; j < 8; j++) {
        const int cb = wc * 4 + j * 16;
        GRAM_DOT(cb);
        float g0[4], g1[4];
        #pragma unroll
        for (int q = 0; q < 4; q++) {
            g0[q] = ex2f_(fmaf(a[0][q], L2E, -C));
            g1[q] = ex2f_(fmaf(a[1][q], L2E, -C));
        }
        float4* gp = (float4*)(gtile + ((j * 256 + tid) << 3));
        gp[0] = make_float4(g0[0], g0[1], g0[2], g0[3]);
        gp[1] = make_float4(g1[0], g1[1], g1[2], g1[3]);
        #pragma unroll
        for (int q = 0; q < 4; q++) {
            s0 += g0[q];
            s1 += g1[q];
            ccol[j * 4 + q] += g0[q] + g1[q];
        }
    }
    sred[wc][nloc] = s0;
    sred[wc][nloc + 1] = s1;
    if (offd) {
        float cs = butterfly32_(ccol, lane);   // lane l holds slot l = j*4+q
        scol[rhalf][wc * 4 + (lane & 3) + 16 * (lane >> 2)] = cs;
    }
    __syncthreads();
    if (tid < 128) {
        float s = sred[0][tid] + sred[1][tid] + sred[2][tid] + sred[3][tid];
        atomicAdd(&g_s[b * NN + ti * 128 + tid], s);
        if (offd) atomicAdd(&g_s[colbase + tid], scol[0][tid] + scol[1][tid]);
    }
}

// ---------------------------------------------------------------------------
// K3: column sums of P from stored g. P_nm = g*w_n, w = 1/S.
// Consumer mapping: hoisted coalesced loads, 8 cols/thread per jj.
// ---------------------------------------------------------------------------
__global__ void __launch_bounds__(256) k3_colsum() {
    __shared__ float wv[128];
    __shared__ float cred[4][128];
    __shared__ float scol[2][128];
    TILE_IDX2();
    if (tid < 128) wv[tid] = 1.0f / g_s[colbase + tid];
    const float w0 = 1.0f / g_s[growR];
    const float w1 = 1.0f / g_s[growR + 1];
    float c0 = 0.f, c1 = 0.f;
    float ccol[32];
    #pragma unroll
    for (int i = 0; i < 32; i++) ccol[i] = 0.f;
    __syncthreads();

    LOAD_G_ALL();
    #pragma unroll
    for (int jj = 0; jj < 4; jj++) {
        const int cb = (jw * 4 + jj) * 16 + wc2 * 8;
        UNPACK_G(jj);
        #pragma unroll
        for (int q = 0; q < 8; q++) {
            float wm = wv[cb + q];
            c0 = fmaf(a0[q], wm, c0);
            c1 = fmaf(a1[q], wm, c1);
            ccol[jj * 8 + q] += fmaf(a0[q], w0, a1[q] * w1);
        }
    }
    cred[w & 3][nloc] = c0;
    cred[w & 3][nloc + 1] = c1;
    if (offd) {
        float cs = butterfly32_(ccol, lane);   // lane l holds slot l = jj*8+q
        const int col = (jw * 4 + (lane >> 3)) * 16 + wc2 * 8 + (lane & 7);
        scol[rhalf][col] = cs;
    }
    __syncthreads();
    if (tid < 128) {
        float c = cred[0][tid] + cred[1][tid] + cred[2][tid] + cred[3][tid];
        atomicAdd(&g_c[b * NN + ti * 128 + tid], c);
        if (offd) atomicAdd(&g_c[colbase + tid], scol[0][tid] + scol[1][tid]);
    }
}

// ---------------------------------------------------------------------------
// K5: out[n,m] = g*(p_n*d_m + p_m*d_n) + [n==m]*d_n*d_m,
//     p = 0.5*w*d, d = rsqrt(0.5*c + 1.5).
// Direct stores: 2x float4 into one 32B-aligned sector (cb multiple of 8).
// Mirror stores: float2 column-contiguous (256B/warp). Hoisted g loads.
// ---------------------------------------------------------------------------
__global__ void __launch_bounds__(256) k5_out(float* __restrict__ out) {
    __shared__ float dcs[128];
    __shared__ float pcs[128];
    TILE_IDX2();
    if (tid < 128) {
        float wm = 1.0f / g_s[colbase + tid];
        float dm = rsq_(fmaf(0.5f, g_c[colbase + tid], 1.5f));
        dcs[tid] = dm;
        pcs[tid] = 0.5f * wm * dm;
    }
    const float d0 = rsq_(fmaf(0.5f, g_c[growR], 1.5f));
    const float d1 = rsq_(fmaf(0.5f, g_c[growR + 1], 1.5f));
    const float p0 = 0.5f * d0 / g_s[growR];
    const float p1 = 0.5f * d1 / g_s[growR + 1];
    const int n0 = ti * 128 + nloc;
    const int m0 = tj * 128;
    float* ob = out + ((size_t)b << 20);
    __syncthreads();

    LOAD_G_ALL();
    #pragma unroll
    for (int jj = 0; jj < 4; jj++) {
        const int cb = (jw * 4 + jj) * 16 + wc2 * 8;
        UNPACK_G(jj);
        float v0[8], v1[8];
        #pragma unroll
        for (int q = 0; q < 8; q++) {
            const float dm = dcs[cb + q], pm = pcs[cb + q];
            v0[q] = a0[q] * fmaf(p0, dm, pm * d0);
            v1[q] = a1[q] * fmaf(p1, dm, pm * d1);
            if (!offd) {   // diagonal tile: self-loop term (ti==tj => compare tile-local)
                if (nloc == cb + q)     v0[q] = fmaf(d0, dm, v0[q]);
                if (nloc + 1 == cb + q) v1[q] = fmaf(d1, dm, v1[q]);
            }
        }
        float* r0 = ob + (size_t)n0 * NN + m0 + cb;
        float* r1 = ob + (size_t)(n0 + 1) * NN + m0 + cb;
        *(float4*)(r0)     = make_float4(v0[0], v0[1], v0[2], v0[3]);
        *(float4*)(r0 + 4) = make_float4(v0[4], v0[5], v0[6], v0[7]);
        *(float4*)(r1)     = make_float4(v1[0], v1[1], v1[2], v1[3]);
        *(float4*)(r1 + 4) = make_float4(v1[4], v1[5], v1[6], v1[7]);
        if (offd) {
            #pragma unroll
            for (int q = 0; q < 8; q++)
                *(float2*)(ob + (size_t)(m0 + cb + q) * NN + n0) = make_float2(v0[q], v1[q]);
        }
    }
}

// ---------------------------------------------------------------------------
extern "C" void kernel_launch(void* const* d_in, const int* in_sizes, int n_in,
                              void* d_out, int out_size)
{
    const float* xt = (const float*)d_in[0];   // (32, 1024, 64)
    const float* W  = (const float*)d_in[1];   // (64, 24)
    const float* bv = (const float*)d_in[2];   // (24,)
    float* out = (float*)d_out;                // (32, 1024, 1024)

    k1_linrelu<<<512, 256>>>(xt, W, bv);
    k2_gram<<<BB * 36, 256>>>();
    k3_colsum<<<BB * 36, 256>>>();
    k5_out<<<BB * 36, 256>>>(out);
}